// round 2
// baseline (speedup 1.0000x reference)
#include <cuda_runtime.h>
#include <cuda_bf16.h>
#include <cstdint>

#define NGROUP 1024
#define GPB 4          // groups per CTA

// ---------------------------------------------------------------------------
// Fused kernel: each CTA handles GPB consecutive groups of one batch row.
// Group boundaries are found by per-thread binary search on the sorted
// segment_ids row (L1/L2-resident, broadcast across the 2048 CTAs that
// search the same 8 rows). Then GPB contiguous-slab mean-pool loops.
// ---------------------------------------------------------------------------
__global__ __launch_bounds__(128)
void pool_fused_kernel(const float4* __restrict__ feats,
                       const int*   __restrict__ seg,
                       float4*      __restrict__ out,
                       float*       __restrict__ counts_out,
                       int S, int Hv) {
    __shared__ int st_sh[GPB + 1];

    const int g0 = blockIdx.x * GPB;
    const int b  = blockIdx.y;
    const int* row = seg + (size_t)b * S;

    // GPB+1 independent lower_bound searches: first s with row[s] >= target
    if (threadIdx.x <= GPB) {
        int target = g0 + threadIdx.x;
        int lo = 0, hi = S;
        while (lo < hi) {
            int mid = (lo + hi) >> 1;
            if (row[mid] < target) lo = mid + 1; else hi = mid;
        }
        st_sh[threadIdx.x] = lo;
    }
    __syncthreads();

    const float4* fb = feats + (size_t)b * S * Hv;
    float4* ob = out + ((size_t)b * NGROUP + g0) * Hv;

    #pragma unroll
    for (int j = 0; j < GPB; ++j) {
        const int s0  = st_sh[j];
        const int cnt = st_sh[j + 1] - s0;
        const float inv = (cnt > 0) ? (1.0f / (float)cnt) : 0.0f;

        for (int v = threadIdx.x; v < Hv; v += blockDim.x) {
            float ax = 0.f, ay = 0.f, az = 0.f, aw = 0.f;
            const float4* p = fb + (size_t)s0 * Hv + v;
            #pragma unroll 4
            for (int t = 0; t < cnt; ++t) {
                float4 x = p[(size_t)t * Hv];
                ax += x.x; ay += x.y; az += x.z; aw += x.w;
            }
            float4 r;
            r.x = ax * inv; r.y = ay * inv; r.z = az * inv; r.w = aw * inv;
            ob[(size_t)j * Hv + v] = r;
        }

        if (counts_out != nullptr && threadIdx.x == 0) {
            counts_out[(size_t)b * NGROUP + g0 + j] = (float)cnt;
        }
    }
}

// ---------------------------------------------------------------------------
extern "C" void kernel_launch(void* const* d_in, const int* in_sizes, int n_in,
                              void* d_out, int out_size) {
    const float* feats = (const float*)d_in[0];
    const int*   seg   = (const int*)d_in[1];
    float* out = (float*)d_out;

    const int n_feat = in_sizes[0];   // B*S*H
    const int n_seg  = in_sizes[1];   // B*S
    const int H = n_feat / n_seg;

    // Does the output buffer include the counts tail [B,G]?
    int B;
    bool has_counts;
    if (out_size % (NGROUP * (H + 1)) == 0) {
        B = out_size / (NGROUP * (H + 1));
        has_counts = true;
        if (B <= 0 || n_seg % B != 0) {
            B = out_size / (NGROUP * H);
            has_counts = false;
        }
    } else {
        B = out_size / (NGROUP * H);
        has_counts = false;
    }
    const int S = n_seg / B;
    const int Hv = H / 4;

    float* counts_out = has_counts ? out + (size_t)B * NGROUP * H : nullptr;

    dim3 grid(NGROUP / GPB, B);
    pool_fused_kernel<<<grid, 128>>>((const float4*)feats, seg,
                                     (float4*)out, counts_out, S, Hv);
}